// round 8
// baseline (speedup 1.0000x reference)
#include <cuda_runtime.h>
#include <cuda_fp16.h>
#include <mma.h>

using namespace nvcuda;

#define NMAX 100000
#define EMAX 1600000
#define FIN  128
#define FOUT 64
#define SCAN_BLOCKS ((NMAX + 255) / 256)   // 391

// ---- scratch (static device globals; no allocations allowed) ----
__device__ int    g_deg[NMAX];
__device__ float  g_dis[NMAX];
__device__ __align__(128) __half g_zs[(size_t)NMAX * FOUT]; // fp16 dis[r]*z[r], 12.8 MB
__device__ float  g_Wc[FIN * FOUT];            // fused weight (tf32-rounded)  W_gcn @ W_fc^T
__device__ float  g_c[FOUT];                   // fused bias (fp32)  W_fc @ b_gcn + b_fc
// CSR scratch
__device__ int    g_off[NMAX + 1];
__device__ int    g_cur[NMAX];
__device__ int    g_bsum[SCAN_BLOCKS];
__device__ int    g_eidx[EMAX];                // source node per CSR slot

// ---------------------------------------------------------------------------
__global__ void k_zero_deg(int N) {
    int i = blockIdx.x * blockDim.x + threadIdx.x;
    if (i < N) g_deg[i] = 0;
}

__global__ void k_deg(const int* __restrict__ ecol, int E) {
    int i = blockIdx.x * blockDim.x + threadIdx.x;
    if (i < E) atomicAdd(&g_deg[ecol[i]], 1);   // RED
}

// ---------------------------------------------------------------------------
// Wc[k][o] = sum_m W_gcn[k][m] * W_fc[o][m]  (stored tf32-rounded, GEMM-only use)
// c[o]     = b_fc[o] + W_fc @ b_gcn           (full fp32)
__global__ void __launch_bounds__(256) k_fuse_w(const float* __restrict__ Wg,
                                                const float* __restrict__ bg,
                                                const float* __restrict__ Wf,
                                                const float* __restrict__ bf) {
    int w = (blockIdx.x * 256 + threadIdx.x) >> 5;
    int lane = threadIdx.x & 31;
    if (w >= (FIN + 1) * FOUT) return;
    int k = w >> 6;           // 0..128 (128 = bias row)
    int o = w & 63;
    const float* wrow = (k < FIN) ? (Wg + (size_t)k * FIN) : bg;
    float s = 0.f;
    #pragma unroll
    for (int m = lane; m < FIN; m += 32) s += wrow[m] * Wf[(size_t)o * FIN + m];
    #pragma unroll
    for (int d = 16; d; d >>= 1) s += __shfl_xor_sync(0xffffffff, s, d);
    if (lane == 0) {
        if (k < FIN) g_Wc[k * FOUT + o] = wmma::__float_to_tf32(s);  // rna-rounded
        else         g_c[o] = s + bf[o];
    }
}

// ---------------------------------------------------------------------------
// CSR build: exclusive scan of g_deg -> g_off / g_cur; also emits g_dis.
__global__ void k_scan1(int N) {
    int i = blockIdx.x * 256 + threadIdx.x;
    int lane = threadIdx.x & 31, wid = threadIdx.x >> 5;
    int orig = (i < N) ? g_deg[i] : 0;
    if (i < N) g_dis[i] = rsqrtf((float)(orig + 1));   // +1 self-loop
    int v = orig;
    #pragma unroll
    for (int d = 1; d < 32; d <<= 1) {
        int n = __shfl_up_sync(0xffffffff, v, d);
        if (lane >= d) v += n;
    }
    __shared__ int ws[8];
    if (lane == 31) ws[wid] = v;
    __syncthreads();
    if (threadIdx.x == 0) {
        int s = 0;
        #pragma unroll
        for (int q = 0; q < 8; q++) { int t = ws[q]; ws[q] = s; s += t; }
        g_bsum[blockIdx.x] = s;
    }
    __syncthreads();
    if (i < N) g_off[i] = v - orig + ws[wid];   // block-local exclusive
}

__global__ void k_scan2(int nb) {               // single block, 512 threads
    __shared__ int s[512];
    int t = threadIdx.x;
    int orig = (t < nb) ? g_bsum[t] : 0;
    s[t] = orig;
    __syncthreads();
    for (int d = 1; d < 512; d <<= 1) {
        int add = (t >= d) ? s[t - d] : 0;
        __syncthreads();
        s[t] += add;
        __syncthreads();
    }
    if (t < nb) g_bsum[t] = s[t] - orig;        // exclusive
}

__global__ void k_scan3(int N, int E) {
    int i = blockIdx.x * 256 + threadIdx.x;
    if (i < N) {
        int off = g_off[i] + g_bsum[blockIdx.x];
        g_off[i] = off;
        g_cur[i] = off;
    }
    if (i == 0) g_off[N] = E;
}

__global__ void k_fill(const int* __restrict__ erow, const int* __restrict__ ecol, int E) {
    int i = blockIdx.x * blockDim.x + threadIdx.x;
    if (i < E) {
        int c = ecol[i];
        int slot = atomicAdd(&g_cur[c], 1);
        g_eidx[slot] = erow[i];
    }
}

// ---------------------------------------------------------------------------
// z = x @ Wc via wmma tf32 (m16n16k8). Block: 8 warps x 16 rows = 128 rows.
// K chunked by 32 in smem. Epilogue via per-warp smem staging:
//   out[i] = c + dis[i]^2 * z[i];  zs[i] = fp16(dis[i]*z[i]).
__global__ void __launch_bounds__(256) k_gemm_init(const float* __restrict__ x,
                                                   float* __restrict__ out, int N) {
    __shared__ float xs[128][40];        // tf32-rounded x chunk (32 k), 20.5 KB
    __shared__ float stage[8][16][20];   // per-warp acc staging, 10.2 KB

    int t = threadIdx.x;
    int w = t >> 5, lane = t & 31;
    int row0 = blockIdx.x * 128;

    wmma::fragment<wmma::accumulator, 16, 16, 8, float> acc[4];
    #pragma unroll
    for (int nt = 0; nt < 4; nt++) wmma::fill_fragment(acc[nt], 0.f);

    for (int kc = 0; kc < FIN; kc += 32) {
        __syncthreads();
        {   // fill x chunk: thread t -> row t/2, 16 floats, tf32-rounded
            int r = t >> 1, half = t & 1;
            int gr = row0 + r;
            const float4* p = (const float4*)&x[(size_t)gr * FIN + kc + half * 16];
            #pragma unroll
            for (int j = 0; j < 4; j++) {
                float4 v = (gr < N) ? p[j] : make_float4(0.f, 0.f, 0.f, 0.f);
                float4 u;
                u.x = wmma::__float_to_tf32(v.x);
                u.y = wmma::__float_to_tf32(v.y);
                u.z = wmma::__float_to_tf32(v.z);
                u.w = wmma::__float_to_tf32(v.w);
                *(float4*)&xs[r][half * 16 + j * 4] = u;
            }
        }
        __syncthreads();

        #pragma unroll
        for (int ks = 0; ks < 4; ks++) {
            wmma::fragment<wmma::matrix_a, 16, 16, 8, wmma::precision::tf32,
                           wmma::row_major> a;
            wmma::load_matrix_sync(a, &xs[w * 16][ks * 8], 40);
            #pragma unroll
            for (int i = 0; i < a.num_elements; i++)
                a.x[i] = wmma::__float_to_tf32(a.x[i]);   // idempotent (pre-rounded)
            #pragma unroll
            for (int nt = 0; nt < 4; nt++) {
                wmma::fragment<wmma::matrix_b, 16, 16, 8, wmma::precision::tf32,
                               wmma::row_major> b;
                wmma::load_matrix_sync(b, &g_Wc[(kc + ks * 8) * FOUT + nt * 16], FOUT);
                #pragma unroll
                for (int i = 0; i < b.num_elements; i++)
                    b.x[i] = wmma::__float_to_tf32(b.x[i]);
                wmma::mma_sync(acc[nt], a, b, acc[nt]);
            }
        }
    }

    // epilogue: stage each 16x16 acc tile through per-warp smem to get row ids
    int r = lane >> 1, ch = lane & 1;      // 16 rows x 2 column-halves
    int gr = row0 + w * 16 + r;
    float d = 0.f, dd = 0.f;
    if (gr < N) { d = g_dis[gr]; dd = d * d; }
    #pragma unroll
    for (int nt = 0; nt < 4; nt++) {
        wmma::store_matrix_sync(&stage[w][0][0], acc[nt], 20, wmma::mem_row_major);
        __syncwarp();
        if (gr < N) {
            float4 v0 = *(float4*)&stage[w][r][ch * 8];
            float4 v1 = *(float4*)&stage[w][r][ch * 8 + 4];
            int col = nt * 16 + ch * 8;
            float4 cb0 = *(const float4*)&g_c[col];
            float4 cb1 = *(const float4*)&g_c[col + 4];
            float4 o0 = make_float4(cb0.x + dd * v0.x, cb0.y + dd * v0.y,
                                    cb0.z + dd * v0.z, cb0.w + dd * v0.w);
            float4 o1 = make_float4(cb1.x + dd * v1.x, cb1.y + dd * v1.y,
                                    cb1.z + dd * v1.z, cb1.w + dd * v1.w);
            *(float4*)&out[(size_t)gr * FOUT + col]     = o0;
            *(float4*)&out[(size_t)gr * FOUT + col + 4] = o1;
            __half2 h0 = __float22half2_rn(make_float2(d * v0.x, d * v0.y));
            __half2 h1 = __float22half2_rn(make_float2(d * v0.z, d * v0.w));
            __half2 h2 = __float22half2_rn(make_float2(d * v1.x, d * v1.y));
            __half2 h3 = __float22half2_rn(make_float2(d * v1.z, d * v1.w));
            uint4 pk;
            pk.x = *(unsigned*)&h0; pk.y = *(unsigned*)&h1;
            pk.z = *(unsigned*)&h2; pk.w = *(unsigned*)&h3;
            *(uint4*)&g_zs[(size_t)gr * FOUT + col] = pk;
        }
        __syncwarp();
    }
}

// ---------------------------------------------------------------------------
// Aggregation: one warp per target node. Lanes hold 2 dims each (64 dims / 32).
__global__ void __launch_bounds__(256) k_aggr(float* __restrict__ out, int N) {
    int w = (blockIdx.x * 256 + threadIdx.x) >> 5;
    int lane = threadIdx.x & 31;
    if (w >= N) return;
    int c = w;
    int off0 = g_off[c], off1 = g_off[c + 1];

    float2 acc = make_float2(0.f, 0.f);
    for (int base = off0; base < off1; base += 32) {
        int cnt = min(32, off1 - base);
        int myE = base + lane;
        int rl = (lane < cnt) ? __ldg(&g_eidx[myE]) : 0;
        int j = 0;
        for (; j + 4 <= cnt; j += 4) {
            int r0 = __shfl_sync(0xffffffff, rl, j);
            int r1 = __shfl_sync(0xffffffff, rl, j + 1);
            int r2 = __shfl_sync(0xffffffff, rl, j + 2);
            int r3 = __shfl_sync(0xffffffff, rl, j + 3);
            unsigned u0 = *(const unsigned*)&g_zs[(size_t)r0 * FOUT + lane * 2];
            unsigned u1 = *(const unsigned*)&g_zs[(size_t)r1 * FOUT + lane * 2];
            unsigned u2 = *(const unsigned*)&g_zs[(size_t)r2 * FOUT + lane * 2];
            unsigned u3 = *(const unsigned*)&g_zs[(size_t)r3 * FOUT + lane * 2];
            float2 f0 = __half22float2(*reinterpret_cast<__half2*>(&u0));
            float2 f1 = __half22float2(*reinterpret_cast<__half2*>(&u1));
            float2 f2 = __half22float2(*reinterpret_cast<__half2*>(&u2));
            float2 f3 = __half22float2(*reinterpret_cast<__half2*>(&u3));
            acc.x += f0.x + f1.x + f2.x + f3.x;
            acc.y += f0.y + f1.y + f2.y + f3.y;
        }
        for (; j < cnt; j++) {
            int r = __shfl_sync(0xffffffff, rl, j);
            unsigned u = *(const unsigned*)&g_zs[(size_t)r * FOUT + lane * 2];
            float2 f = __half22float2(*reinterpret_cast<__half2*>(&u));
            acc.x += f.x; acc.y += f.y;
        }
    }
    if (off1 > off0) {
        float dc = g_dis[c];
        float2* o = (float2*)&out[(size_t)c * FOUT + lane * 2];
        float2 cur = *o;
        cur.x += dc * acc.x;
        cur.y += dc * acc.y;
        *o = cur;
    }
}

// ---------------------------------------------------------------------------
extern "C" void kernel_launch(void* const* d_in, const int* in_sizes, int n_in,
                              void* d_out, int out_size) {
    const float* x  = (const float*)d_in[0];
    const int*   ei = (const int*)d_in[1];
    const float* Wg = (const float*)d_in[2];
    const float* bg = (const float*)d_in[3];
    const float* Wf = (const float*)d_in[4];
    const float* bf = (const float*)d_in[5];
    float* out = (float*)d_out;

    int N = in_sizes[0] / FIN;
    int E = in_sizes[1] / 2;
    const int* erow = ei;        // sources
    const int* ecol = ei + E;    // targets (aggregation index)

    int nb = (N + 255) / 256;    // == SCAN_BLOCKS for N=100000

    k_zero_deg<<<nb, 256>>>(N);
    k_deg<<<(E + 255) / 256, 256>>>(ecol, E);
    k_fuse_w<<<((FIN + 1) * FOUT * 32 + 255) / 256, 256>>>(Wg, bg, Wf, bf);
    k_scan1<<<nb, 256>>>(N);
    k_scan2<<<1, 512>>>(nb);
    k_scan3<<<nb, 256>>>(N, E);
    k_fill<<<(E + 255) / 256, 256>>>(erow, ecol, E);
    k_gemm_init<<<(N + 127) / 128, 256>>>(x, out, N);
    k_aggr<<<(N * 32 + 255) / 256, 256>>>(out, N);
}

// round 9
// speedup vs baseline: 1.2056x; 1.2056x over previous
#include <cuda_runtime.h>
#include <cuda_fp16.h>

#define NMAX 100000
#define EMAX 1600000
#define FIN  128
#define FOUT 64
#define SCAN_BLOCKS ((NMAX + 255) / 256)   // 391

// ---- scratch (static device globals; no allocations allowed) ----
__device__ int    g_deg[NMAX];
__device__ float  g_dis[NMAX];
__device__ __align__(128) __half g_zs[(size_t)NMAX * FOUT]; // fp16 dis[r]*z[r], 12.8 MB
__device__ float  g_Wc[FIN * FOUT];            // fused weight  W_gcn @ W_fc^T
__device__ float  g_c[FOUT];                   // fused bias    W_fc @ b_gcn + b_fc
// CSR scratch
__device__ int    g_off[NMAX + 1];
__device__ int    g_cur[NMAX];
__device__ int    g_bsum[SCAN_BLOCKS];
__device__ int    g_eidx[EMAX];                // source node per CSR slot

// ---------------------------------------------------------------------------
__global__ void k_deg(const int* __restrict__ ecol, int E) {
    int i = blockIdx.x * blockDim.x + threadIdx.x;
    if (i < E) atomicAdd(&g_deg[ecol[i]], 1);   // RED
}

// ---------------------------------------------------------------------------
// Wc[k][o] = sum_m W_gcn[k][m] * W_fc[o][m];  c[o] = b_fc[o] + W_fc @ b_gcn
__global__ void __launch_bounds__(256) k_fuse_w(const float* __restrict__ Wg,
                                                const float* __restrict__ bg,
                                                const float* __restrict__ Wf,
                                                const float* __restrict__ bf) {
    int w = (blockIdx.x * 256 + threadIdx.x) >> 5;
    int lane = threadIdx.x & 31;
    if (w >= (FIN + 1) * FOUT) return;
    int k = w >> 6;           // 0..128 (128 = bias row)
    int o = w & 63;
    const float* wrow = (k < FIN) ? (Wg + (size_t)k * FIN) : bg;
    float s = 0.f;
    #pragma unroll
    for (int m = lane; m < FIN; m += 32) s += wrow[m] * Wf[(size_t)o * FIN + m];
    #pragma unroll
    for (int d = 16; d; d >>= 1) s += __shfl_xor_sync(0xffffffff, s, d);
    if (lane == 0) {
        if (k < FIN) g_Wc[k * FOUT + o] = s;
        else         g_c[o] = s + bf[o];
    }
}

// ---------------------------------------------------------------------------
// CSR build: scan1 emits block-local exclusive scan + per-block totals + dis.
__global__ void k_scan1(int N) {
    int i = blockIdx.x * 256 + threadIdx.x;
    int lane = threadIdx.x & 31, wid = threadIdx.x >> 5;
    int orig = (i < N) ? g_deg[i] : 0;
    if (i < N) g_dis[i] = rsqrtf((float)(orig + 1));   // +1 self-loop
    int v = orig;
    #pragma unroll
    for (int d = 1; d < 32; d <<= 1) {
        int n = __shfl_up_sync(0xffffffff, v, d);
        if (lane >= d) v += n;
    }
    __shared__ int ws[8];
    if (lane == 31) ws[wid] = v;
    __syncthreads();
    if (threadIdx.x == 0) {
        int s = 0;
        #pragma unroll
        for (int q = 0; q < 8; q++) { int t = ws[q]; ws[q] = s; s += t; }
        g_bsum[blockIdx.x] = s;
    }
    __syncthreads();
    if (i < N) g_off[i] = v - orig + ws[wid];   // block-local exclusive
}

// scan3: each block reduces bsum[0..bid-1] itself (391 ints — cheap), then
// finalizes offsets and cursors. Replaces the old scan2+scan3 pair.
__global__ void __launch_bounds__(256) k_scan3(int N, int E) {
    __shared__ int sh[256];
    int t = threadIdx.x, bid = blockIdx.x;
    int s = 0;
    for (int q = t; q < bid; q += 256) s += g_bsum[q];
    sh[t] = s;
    __syncthreads();
    #pragma unroll
    for (int d = 128; d; d >>= 1) {
        if (t < d) sh[t] += sh[t + d];
        __syncthreads();
    }
    int base = sh[0];
    int i = bid * 256 + t;
    if (i < N) {
        int off = g_off[i] + base;
        g_off[i] = off;
        g_cur[i] = off;
    }
    if (i == 0) g_off[N] = E;
}

__global__ void k_fill(const int* __restrict__ erow, const int* __restrict__ ecol, int E) {
    int i = blockIdx.x * blockDim.x + threadIdx.x;
    if (i < E) {
        int c = ecol[i];
        int slot = atomicAdd(&g_cur[c], 1);
        g_eidx[slot] = erow[i];
    }
}

// ---------------------------------------------------------------------------
// z = x @ Wc  (100000 x 64, K=128), fp32 via packed fma.rn.f32x2 (round-5 proven).
// Epilogue: out[i] = c + dis[i]^2 * z[i]; zs[i] = fp16(dis[i]*z[i]).
__global__ void __launch_bounds__(256) k_gemm_init(const float* __restrict__ x,
                                                   float* __restrict__ out, int N) {
    __shared__ float Wcs[FIN][FOUT];
    __shared__ float xs[8][256 + 4];

    int t = threadIdx.x;
    {
        const float4* s = (const float4*)g_Wc;
        float4*       d = (float4*)&Wcs[0][0];
        #pragma unroll
        for (int i = 0; i < (FIN * FOUT / 4) / 256; i++) d[t + i * 256] = s[t + i * 256];
    }

    int row0 = blockIdx.x * 256;
    int tm = t >> 4;
    int tn = t & 15;

    unsigned long long acc[8][4];
    #pragma unroll
    for (int i = 0; i < 8; i++)
        #pragma unroll
        for (int j = 0; j < 4; j++) acc[i][j] = 0ULL;

    for (int kc = 0; kc < FIN; kc += 8) {
        __syncthreads();
        {
            int gr = row0 + t;
            float4 a = make_float4(0.f, 0.f, 0.f, 0.f), b = a;
            if (gr < N) {
                const float4* p = (const float4*)&x[(size_t)gr * FIN + kc];
                a = p[0]; b = p[1];
            }
            xs[0][t] = a.x; xs[1][t] = a.y; xs[2][t] = a.z; xs[3][t] = a.w;
            xs[4][t] = b.x; xs[5][t] = b.y; xs[6][t] = b.z; xs[7][t] = b.w;
        }
        __syncthreads();

        #pragma unroll
        for (int k = 0; k < 8; k++) {
            float4 bv = *(const float4*)&Wcs[kc + k][tn * 4];
            unsigned long long b2[4];
            asm("mov.b64 %0, {%1, %1};" : "=l"(b2[0]) : "f"(bv.x));
            asm("mov.b64 %0, {%1, %1};" : "=l"(b2[1]) : "f"(bv.y));
            asm("mov.b64 %0, {%1, %1};" : "=l"(b2[2]) : "f"(bv.z));
            asm("mov.b64 %0, {%1, %1};" : "=l"(b2[3]) : "f"(bv.w));

            const ulonglong2* ap = (const ulonglong2*)&xs[k][tm * 16];
            ulonglong2 p0 = ap[0], p1 = ap[1], p2 = ap[2], p3 = ap[3];
            unsigned long long av[8] = {p0.x, p0.y, p1.x, p1.y, p2.x, p2.y, p3.x, p3.y};

            #pragma unroll
            for (int i = 0; i < 8; i++)
                #pragma unroll
                for (int j = 0; j < 4; j++)
                    asm("fma.rn.f32x2 %0, %1, %2, %0;"
                        : "+l"(acc[i][j]) : "l"(av[i]), "l"(b2[j]));
        }
    }

    float4 cb = *(const float4*)&g_c[tn * 4];
    #pragma unroll
    for (int i = 0; i < 8; i++) {
        int r = row0 + tm * 16 + 2 * i;
        float2 c0 = *(float2*)&acc[i][0];
        float2 c1 = *(float2*)&acc[i][1];
        float2 c2 = *(float2*)&acc[i][2];
        float2 c3 = *(float2*)&acc[i][3];
        #pragma unroll
        for (int s = 0; s < 2; s++) {
            int rr = r + s;
            if (rr >= N) break;
            float4 zv = s ? make_float4(c0.y, c1.y, c2.y, c3.y)
                          : make_float4(c0.x, c1.x, c2.x, c3.x);
            float d = g_dis[rr]; float dd = d * d;
            *(float4*)&out[(size_t)rr * FOUT + tn * 4] =
                make_float4(cb.x + dd * zv.x, cb.y + dd * zv.y,
                            cb.z + dd * zv.z, cb.w + dd * zv.w);
            __half2 h0 = __float22half2_rn(make_float2(d * zv.x, d * zv.y));
            __half2 h1 = __float22half2_rn(make_float2(d * zv.z, d * zv.w));
            uint2 pk;
            pk.x = *(unsigned int*)&h0;
            pk.y = *(unsigned int*)&h1;
            *(uint2*)&g_zs[(size_t)rr * FOUT + tn * 4] = pk;
        }
    }
}

// ---------------------------------------------------------------------------
// Aggregation: one warp per target node. Lanes hold 2 dims each (64 dims / 32).
__global__ void __launch_bounds__(256) k_aggr(float* __restrict__ out, int N) {
    int w = (blockIdx.x * 256 + threadIdx.x) >> 5;
    int lane = threadIdx.x & 31;
    if (w >= N) return;
    int c = w;
    int off0 = g_off[c], off1 = g_off[c + 1];

    float2 acc = make_float2(0.f, 0.f);
    for (int base = off0; base < off1; base += 32) {
        int cnt = min(32, off1 - base);
        int myE = base + lane;
        int rl = (lane < cnt) ? __ldg(&g_eidx[myE]) : 0;
        int j = 0;
        for (; j + 4 <= cnt; j += 4) {
            int r0 = __shfl_sync(0xffffffff, rl, j);
            int r1 = __shfl_sync(0xffffffff, rl, j + 1);
            int r2 = __shfl_sync(0xffffffff, rl, j + 2);
            int r3 = __shfl_sync(0xffffffff, rl, j + 3);
            unsigned u0 = *(const unsigned*)&g_zs[(size_t)r0 * FOUT + lane * 2];
            unsigned u1 = *(const unsigned*)&g_zs[(size_t)r1 * FOUT + lane * 2];
            unsigned u2 = *(const unsigned*)&g_zs[(size_t)r2 * FOUT + lane * 2];
            unsigned u3 = *(const unsigned*)&g_zs[(size_t)r3 * FOUT + lane * 2];
            float2 f0 = __half22float2(*reinterpret_cast<__half2*>(&u0));
            float2 f1 = __half22float2(*reinterpret_cast<__half2*>(&u1));
            float2 f2 = __half22float2(*reinterpret_cast<__half2*>(&u2));
            float2 f3 = __half22float2(*reinterpret_cast<__half2*>(&u3));
            acc.x += f0.x + f1.x + f2.x + f3.x;
            acc.y += f0.y + f1.y + f2.y + f3.y;
        }
        for (; j < cnt; j++) {
            int r = __shfl_sync(0xffffffff, rl, j);
            unsigned u = *(const unsigned*)&g_zs[(size_t)r * FOUT + lane * 2];
            float2 f = __half22float2(*reinterpret_cast<__half2*>(&u));
            acc.x += f.x; acc.y += f.y;
        }
    }
    if (off1 > off0) {
        float dc = g_dis[c];
        float2* o = (float2*)&out[(size_t)c * FOUT + lane * 2];
        float2 cur = *o;
        cur.x += dc * acc.x;
        cur.y += dc * acc.y;
        *o = cur;
    }
}

// ---------------------------------------------------------------------------
// Forked-stream schedule (graph-capturable):
//   stream0: memset(deg) -> deg -> scan1 -> scan3 -> fill -> [wait gemm] -> aggr
//   s2:      fuse_w (|| deg) -> [wait scan1] -> gemm_init
extern "C" void kernel_launch(void* const* d_in, const int* in_sizes, int n_in,
                              void* d_out, int out_size) {
    const float* x  = (const float*)d_in[0];
    const int*   ei = (const int*)d_in[1];
    const float* Wg = (const float*)d_in[2];
    const float* bg = (const float*)d_in[3];
    const float* Wf = (const float*)d_in[4];
    const float* bf = (const float*)d_in[5];
    float* out = (float*)d_out;

    int N = in_sizes[0] / FIN;
    int E = in_sizes[1] / 2;
    const int* erow = ei;        // sources
    const int* ecol = ei + E;    // targets (aggregation index)

    int nb = (N + 255) / 256;

    // Fresh stream/events per call (kernel_launch runs only a few times;
    // never destroyed — destroying a capturing stream is an error).
    cudaStream_t s2;
    cudaStreamCreateWithFlags(&s2, cudaStreamNonBlocking);
    cudaEvent_t eFork, eDis, eSide;
    cudaEventCreateWithFlags(&eFork, cudaEventDisableTiming);
    cudaEventCreateWithFlags(&eDis,  cudaEventDisableTiming);
    cudaEventCreateWithFlags(&eSide, cudaEventDisableTiming);

    void* degPtr = nullptr;
    cudaGetSymbolAddress(&degPtr, g_deg);

    // fork: side branch does the dense prep
    cudaEventRecord(eFork, 0);
    cudaStreamWaitEvent(s2, eFork, 0);
    k_fuse_w<<<((FIN + 1) * FOUT * 32 + 255) / 256, 256, 0, s2>>>(Wg, bg, Wf, bf);

    // main branch: degree pipeline
    cudaMemsetAsync(degPtr, 0, (size_t)N * sizeof(int), 0);
    k_deg<<<(E + 255) / 256, 256>>>(ecol, E);
    k_scan1<<<nb, 256>>>(N);
    cudaEventRecord(eDis, 0);

    // side branch: GEMM (needs g_dis from scan1 + Wc from fuse_w)
    cudaStreamWaitEvent(s2, eDis, 0);
    k_gemm_init<<<(N + 255) / 256, 256, 0, s2>>>(x, out, N);
    cudaEventRecord(eSide, s2);

    // main branch continues: CSR finalize + fill (independent of GEMM)
    k_scan3<<<nb, 256>>>(N, E);
    k_fill<<<(E + 255) / 256, 256>>>(erow, ecol, E);

    // join, then aggregate
    cudaStreamWaitEvent(0, eSide, 0);
    k_aggr<<<(N * 32 + 255) / 256, 256>>>(out, N);
}

// round 10
// speedup vs baseline: 1.2789x; 1.0607x over previous
#include <cuda_runtime.h>
#include <cuda_fp16.h>

#define NMAX 100000
#define EMAX 1600000
#define FIN  128
#define FOUT 64
#define SCAN_BLOCKS ((NMAX + 255) / 256)   // 391

// ---- scratch (static device globals; no allocations allowed) ----
__device__ int    g_deg[NMAX];
__device__ float  g_dis[NMAX];
__device__ __align__(128) __half g_zs[(size_t)NMAX * FOUT]; // fp16 z, then dis*z after k_scale
__device__ float  g_Wc[FIN * FOUT];            // fused weight  W_gcn @ W_fc^T
__device__ float  g_c[FOUT];                   // fused bias    W_fc @ b_gcn + b_fc
// CSR scratch
__device__ int    g_off[NMAX + 1];
__device__ int    g_cur[NMAX];
__device__ int    g_bsum[SCAN_BLOCKS];
__device__ int    g_eidx[EMAX];                // source node per CSR slot

// ---------------------------------------------------------------------------
__global__ void k_deg(const int* __restrict__ ecol, int E) {
    int i = blockIdx.x * blockDim.x + threadIdx.x;
    if (i < E) atomicAdd(&g_deg[ecol[i]], 1);   // RED
}

// ---------------------------------------------------------------------------
// Wc[k][o] = sum_m W_gcn[k][m] * W_fc[o][m];  c[o] = b_fc[o] + W_fc @ b_gcn
__global__ void __launch_bounds__(256) k_fuse_w(const float* __restrict__ Wg,
                                                const float* __restrict__ bg,
                                                const float* __restrict__ Wf,
                                                const float* __restrict__ bf) {
    int w = (blockIdx.x * 256 + threadIdx.x) >> 5;
    int lane = threadIdx.x & 31;
    if (w >= (FIN + 1) * FOUT) return;
    int k = w >> 6;           // 0..128 (128 = bias row)
    int o = w & 63;
    const float* wrow = (k < FIN) ? (Wg + (size_t)k * FIN) : bg;
    float s = 0.f;
    #pragma unroll
    for (int m = lane; m < FIN; m += 32) s += wrow[m] * Wf[(size_t)o * FIN + m];
    #pragma unroll
    for (int d = 16; d; d >>= 1) s += __shfl_xor_sync(0xffffffff, s, d);
    if (lane == 0) {
        if (k < FIN) g_Wc[k * FOUT + o] = s;
        else         g_c[o] = s + bf[o];
    }
}

// ---------------------------------------------------------------------------
// CSR build: scan1 emits block-local exclusive scan + per-block totals + dis.
__global__ void k_scan1(int N) {
    int i = blockIdx.x * 256 + threadIdx.x;
    int lane = threadIdx.x & 31, wid = threadIdx.x >> 5;
    int orig = (i < N) ? g_deg[i] : 0;
    if (i < N) g_dis[i] = rsqrtf((float)(orig + 1));   // +1 self-loop
    int v = orig;
    #pragma unroll
    for (int d = 1; d < 32; d <<= 1) {
        int n = __shfl_up_sync(0xffffffff, v, d);
        if (lane >= d) v += n;
    }
    __shared__ int ws[8];
    if (lane == 31) ws[wid] = v;
    __syncthreads();
    if (threadIdx.x == 0) {
        int s = 0;
        #pragma unroll
        for (int q = 0; q < 8; q++) { int t = ws[q]; ws[q] = s; s += t; }
        g_bsum[blockIdx.x] = s;
    }
    __syncthreads();
    if (i < N) g_off[i] = v - orig + ws[wid];   // block-local exclusive
}

// scan3: each block reduces bsum[0..bid-1] itself, finalizes offsets/cursors.
__global__ void __launch_bounds__(256) k_scan3(int N, int E) {
    __shared__ int sh[256];
    int t = threadIdx.x, bid = blockIdx.x;
    int s = 0;
    for (int q = t; q < bid; q += 256) s += g_bsum[q];
    sh[t] = s;
    __syncthreads();
    #pragma unroll
    for (int d = 128; d; d >>= 1) {
        if (t < d) sh[t] += sh[t + d];
        __syncthreads();
    }
    int base = sh[0];
    int i = bid * 256 + t;
    if (i < N) {
        int off = g_off[i] + base;
        g_off[i] = off;
        g_cur[i] = off;
    }
    if (i == 0) g_off[N] = E;
}

__global__ void k_fill(const int* __restrict__ erow, const int* __restrict__ ecol, int E) {
    int i = blockIdx.x * blockDim.x + threadIdx.x;
    if (i < E) {
        int c = ecol[i];
        int slot = atomicAdd(&g_cur[c], 1);
        g_eidx[slot] = erow[i];
    }
}

// ---------------------------------------------------------------------------
// z = x @ Wc, fp32 f32x2 FMA; writes RAW fp16 z only (no dis, no out).
// MT=128 rows/block, thread tile 8 rows x 4 cols -> 32 acc regs, 3 CTAs/SM.
__global__ void __launch_bounds__(256) k_gemm(const float* __restrict__ x, int N) {
    __shared__ __align__(16) float Wcs[FIN][FOUT];      // 32 KB
    __shared__ __align__(16) float xs[8][132];          // 4.2 KB

    int t = threadIdx.x;
    {
        const float4* s = (const float4*)g_Wc;
        float4*       d = (float4*)&Wcs[0][0];
        #pragma unroll
        for (int i = 0; i < (FIN * FOUT / 4) / 256; i++) d[t + i * 256] = s[t + i * 256];
    }

    int row0 = blockIdx.x * 128;
    int tm = t >> 4;      // 0..15 -> rows tm*8..+7
    int tn = t & 15;      // cols tn*4..+3
    int lr = t >> 1, lh = t & 1;   // loader: row, 16B-half of 32B k-slab

    unsigned long long acc[4][4];
    #pragma unroll
    for (int i = 0; i < 4; i++)
        #pragma unroll
        for (int j = 0; j < 4; j++) acc[i][j] = 0ULL;

    for (int kc = 0; kc < FIN; kc += 8) {
        __syncthreads();
        {
            int gr = row0 + lr;
            float4 a = make_float4(0.f, 0.f, 0.f, 0.f);
            if (gr < N)
                a = ((const float4*)&x[(size_t)gr * FIN + kc])[lh];
            xs[lh * 4 + 0][lr] = a.x;
            xs[lh * 4 + 1][lr] = a.y;
            xs[lh * 4 + 2][lr] = a.z;
            xs[lh * 4 + 3][lr] = a.w;
        }
        __syncthreads();

        #pragma unroll
        for (int k = 0; k < 8; k++) {
            float4 bv = *(const float4*)&Wcs[kc + k][tn * 4];
            unsigned long long b2[4];
            asm("mov.b64 %0, {%1, %1};" : "=l"(b2[0]) : "f"(bv.x));
            asm("mov.b64 %0, {%1, %1};" : "=l"(b2[1]) : "f"(bv.y));
            asm("mov.b64 %0, {%1, %1};" : "=l"(b2[2]) : "f"(bv.z));
            asm("mov.b64 %0, {%1, %1};" : "=l"(b2[3]) : "f"(bv.w));

            const ulonglong2* ap = (const ulonglong2*)&xs[k][tm * 8];
            ulonglong2 p0 = ap[0], p1 = ap[1];
            unsigned long long av[4] = {p0.x, p0.y, p1.x, p1.y};

            #pragma unroll
            for (int i = 0; i < 4; i++)
                #pragma unroll
                for (int j = 0; j < 4; j++)
                    asm("fma.rn.f32x2 %0, %1, %2, %0;"
                        : "+l"(acc[i][j]) : "l"(av[i]), "l"(b2[j]));
        }
    }

    // epilogue: raw fp16 z
    #pragma unroll
    for (int i = 0; i < 4; i++) {
        int r = row0 + tm * 8 + 2 * i;
        float2 c0 = *(float2*)&acc[i][0];
        float2 c1 = *(float2*)&acc[i][1];
        float2 c2 = *(float2*)&acc[i][2];
        float2 c3 = *(float2*)&acc[i][3];
        #pragma unroll
        for (int s = 0; s < 2; s++) {
            int rr = r + s;
            if (rr >= N) break;
            float4 zv = s ? make_float4(c0.y, c1.y, c2.y, c3.y)
                          : make_float4(c0.x, c1.x, c2.x, c3.x);
            __half2 h0 = __float22half2_rn(make_float2(zv.x, zv.y));
            __half2 h1 = __float22half2_rn(make_float2(zv.z, zv.w));
            uint2 pk;
            pk.x = *(unsigned int*)&h0;
            pk.y = *(unsigned int*)&h1;
            *(uint2*)&g_zs[(size_t)rr * FOUT + tn * 4] = pk;
        }
    }
}

// ---------------------------------------------------------------------------
// zs[r] *= dis[r]  (in-place fp16, fp32 math). 8 threads per row, 8 halves each.
__global__ void __launch_bounds__(256) k_scale(int N) {
    int gid = blockIdx.x * 256 + threadIdx.x;
    int row = gid >> 3;
    if (row >= N) return;
    float d = g_dis[row];
    uint4* p = (uint4*)&g_zs[(size_t)row * FOUT + (gid & 7) * 8];
    uint4 u = *p;
    unsigned* uu = (unsigned*)&u;
    #pragma unroll
    for (int i = 0; i < 4; i++) {
        float2 f = __half22float2(*reinterpret_cast<__half2*>(&uu[i]));
        __half2 h = __float22half2_rn(make_float2(d * f.x, d * f.y));
        uu[i] = *(unsigned*)&h;
    }
    *p = u;
}

// ---------------------------------------------------------------------------
// Aggregation incl. self-loop: out[c] = cb + dis[c] * (zs[c] + sum_r zs[r]).
// One warp per node; lanes hold 2 dims each. No out-read.
__global__ void __launch_bounds__(256) k_aggr(float* __restrict__ out, int N) {
    int w = (blockIdx.x * 256 + threadIdx.x) >> 5;
    int lane = threadIdx.x & 31;
    if (w >= N) return;
    int c = w;
    int off0 = g_off[c], off1 = g_off[c + 1];

    // self-loop message
    unsigned us = *(const unsigned*)&g_zs[(size_t)c * FOUT + lane * 2];
    float2 acc = __half22float2(*reinterpret_cast<__half2*>(&us));

    for (int base = off0; base < off1; base += 32) {
        int cnt = min(32, off1 - base);
        int myE = base + lane;
        int rl = (lane < cnt) ? __ldg(&g_eidx[myE]) : 0;
        int j = 0;
        for (; j + 4 <= cnt; j += 4) {
            int r0 = __shfl_sync(0xffffffff, rl, j);
            int r1 = __shfl_sync(0xffffffff, rl, j + 1);
            int r2 = __shfl_sync(0xffffffff, rl, j + 2);
            int r3 = __shfl_sync(0xffffffff, rl, j + 3);
            unsigned u0 = *(const unsigned*)&g_zs[(size_t)r0 * FOUT + lane * 2];
            unsigned u1 = *(const unsigned*)&g_zs[(size_t)r1 * FOUT + lane * 2];
            unsigned u2 = *(const unsigned*)&g_zs[(size_t)r2 * FOUT + lane * 2];
            unsigned u3 = *(const unsigned*)&g_zs[(size_t)r3 * FOUT + lane * 2];
            float2 f0 = __half22float2(*reinterpret_cast<__half2*>(&u0));
            float2 f1 = __half22float2(*reinterpret_cast<__half2*>(&u1));
            float2 f2 = __half22float2(*reinterpret_cast<__half2*>(&u2));
            float2 f3 = __half22float2(*reinterpret_cast<__half2*>(&u3));
            acc.x += f0.x + f1.x + f2.x + f3.x;
            acc.y += f0.y + f1.y + f2.y + f3.y;
        }
        for (; j < cnt; j++) {
            int r = __shfl_sync(0xffffffff, rl, j);
            unsigned u = *(const unsigned*)&g_zs[(size_t)r * FOUT + lane * 2];
            float2 f = __half22float2(*reinterpret_cast<__half2*>(&u));
            acc.x += f.x; acc.y += f.y;
        }
    }
    float dc = g_dis[c];
    float2 cb = *(const float2*)&g_c[lane * 2];
    float2 ov;
    ov.x = cb.x + dc * acc.x;
    ov.y = cb.y + dc * acc.y;
    *(float2*)&out[(size_t)c * FOUT + lane * 2] = ov;
}

// ---------------------------------------------------------------------------
// Forked-stream schedule (graph-capturable):
//   stream0: memset(deg) -> deg -> scan1 -> scan3 -> fill -> [wait gemm] -> scale -> aggr
//   s2:      fuse_w -> gemm  (fully parallel with CSR pipeline; no dis needed)
extern "C" void kernel_launch(void* const* d_in, const int* in_sizes, int n_in,
                              void* d_out, int out_size) {
    const float* x  = (const float*)d_in[0];
    const int*   ei = (const int*)d_in[1];
    const float* Wg = (const float*)d_in[2];
    const float* bg = (const float*)d_in[3];
    const float* Wf = (const float*)d_in[4];
    const float* bf = (const float*)d_in[5];
    float* out = (float*)d_out;

    int N = in_sizes[0] / FIN;
    int E = in_sizes[1] / 2;
    const int* erow = ei;        // sources
    const int* ecol = ei + E;    // targets (aggregation index)

    int nb = (N + 255) / 256;

    cudaStream_t s2;
    cudaStreamCreateWithFlags(&s2, cudaStreamNonBlocking);
    cudaEvent_t eFork, eSide;
    cudaEventCreateWithFlags(&eFork, cudaEventDisableTiming);
    cudaEventCreateWithFlags(&eSide, cudaEventDisableTiming);

    void* degPtr = nullptr;
    cudaGetSymbolAddress(&degPtr, g_deg);

    // fork: side branch = dense pipeline (independent of graph structure)
    cudaEventRecord(eFork, 0);
    cudaStreamWaitEvent(s2, eFork, 0);
    k_fuse_w<<<((FIN + 1) * FOUT * 32 + 255) / 256, 256, 0, s2>>>(Wg, bg, Wf, bf);
    k_gemm<<<(N + 127) / 128, 256, 0, s2>>>(x, N);
    cudaEventRecord(eSide, s2);

    // main branch: degree + CSR pipeline
    cudaMemsetAsync(degPtr, 0, (size_t)N * sizeof(int), 0);
    k_deg<<<(E + 255) / 256, 256>>>(ecol, E);
    k_scan1<<<nb, 256>>>(N);
    k_scan3<<<nb, 256>>>(N, E);
    k_fill<<<(E + 255) / 256, 256>>>(erow, ecol, E);

    // join: scale (needs gemm + dis), then aggregate
    cudaStreamWaitEvent(0, eSide, 0);
    k_scale<<<(N * 8 + 255) / 256, 256>>>(N);
    k_aggr<<<(N * 32 + 255) / 256, 256>>>(out, N);
}

// round 11
// speedup vs baseline: 1.4752x; 1.1535x over previous
#include <cuda_runtime.h>
#include <cuda_fp16.h>
#include <mma.h>

#define NMAX 100000
#define EMAX 1600000
#define FIN  128
#define FOUT 64
#define SCAN_BLOCKS ((NMAX + 255) / 256)   // 391

// ---- scratch (static device globals; no allocations allowed) ----
__device__ int    g_deg[NMAX];
__device__ float  g_dis[NMAX];
__device__ __align__(128) __half g_zs[(size_t)NMAX * FOUT]; // fp16 z, then dis*z after k_scale
__device__ float  g_Wc[FIN * FOUT];            // fused weight (tf32-rounded)
__device__ float  g_c[FOUT];                   // fused bias (fp32)
// CSR scratch
__device__ int    g_off[NMAX + 1];
__device__ int    g_cur[NMAX];
__device__ int    g_bsum[SCAN_BLOCKS];
__device__ int    g_eidx[EMAX];                // source node per CSR slot

// ---------------------------------------------------------------------------
__global__ void k_deg(const int* __restrict__ ecol, int E) {
    int i = blockIdx.x * blockDim.x + threadIdx.x;
    if (i < E) atomicAdd(&g_deg[ecol[i]], 1);   // RED
}

// ---------------------------------------------------------------------------
// Wc[k][o] = sum_m W_gcn[k][m] * W_fc[o][m]  (stored tf32-rna-rounded)
// c[o]     = b_fc[o] + W_fc @ b_gcn           (full fp32)
__global__ void __launch_bounds__(256) k_fuse_w(const float* __restrict__ Wg,
                                                const float* __restrict__ bg,
                                                const float* __restrict__ Wf,
                                                const float* __restrict__ bf) {
    int w = (blockIdx.x * 256 + threadIdx.x) >> 5;
    int lane = threadIdx.x & 31;
    if (w >= (FIN + 1) * FOUT) return;
    int k = w >> 6;
    int o = w & 63;
    const float* wrow = (k < FIN) ? (Wg + (size_t)k * FIN) : bg;
    float s = 0.f;
    #pragma unroll
    for (int m = lane; m < FIN; m += 32) s += wrow[m] * Wf[(size_t)o * FIN + m];
    #pragma unroll
    for (int d = 16; d; d >>= 1) s += __shfl_xor_sync(0xffffffff, s, d);
    if (lane == 0) {
        if (k < FIN) g_Wc[k * FOUT + o] = nvcuda::wmma::__float_to_tf32(s);
        else         g_c[o] = s + bf[o];
    }
}

// ---------------------------------------------------------------------------
// CSR build: scan1 emits block-local exclusive scan + per-block totals + dis.
__global__ void k_scan1(int N) {
    int i = blockIdx.x * 256 + threadIdx.x;
    int lane = threadIdx.x & 31, wid = threadIdx.x >> 5;
    int orig = (i < N) ? g_deg[i] : 0;
    if (i < N) g_dis[i] = rsqrtf((float)(orig + 1));   // +1 self-loop
    int v = orig;
    #pragma unroll
    for (int d = 1; d < 32; d <<= 1) {
        int n = __shfl_up_sync(0xffffffff, v, d);
        if (lane >= d) v += n;
    }
    __shared__ int ws[8];
    if (lane == 31) ws[wid] = v;
    __syncthreads();
    if (threadIdx.x == 0) {
        int s = 0;
        #pragma unroll
        for (int q = 0; q < 8; q++) { int t = ws[q]; ws[q] = s; s += t; }
        g_bsum[blockIdx.x] = s;
    }
    __syncthreads();
    if (i < N) g_off[i] = v - orig + ws[wid];
}

__global__ void __launch_bounds__(256) k_scan3(int N, int E) {
    __shared__ int sh[256];
    int t = threadIdx.x, bid = blockIdx.x;
    int s = 0;
    for (int q = t; q < bid; q += 256) s += g_bsum[q];
    sh[t] = s;
    __syncthreads();
    #pragma unroll
    for (int d = 128; d; d >>= 1) {
        if (t < d) sh[t] += sh[t + d];
        __syncthreads();
    }
    int base = sh[0];
    int i = bid * 256 + t;
    if (i < N) {
        int off = g_off[i] + base;
        g_off[i] = off;
        g_cur[i] = off;
    }
    if (i == 0) g_off[N] = E;
}

__global__ void k_fill(const int* __restrict__ erow, const int* __restrict__ ecol, int E) {
    int i = blockIdx.x * blockDim.x + threadIdx.x;
    if (i < E) {
        int c = ecol[i];
        int slot = atomicAdd(&g_cur[c], 1);
        g_eidx[slot] = erow[i];
    }
}

// ---------------------------------------------------------------------------
// z = x @ Wc via tf32 mma.sync m16n8k8 (inline asm, documented fragment maps).
// Block: 8 warps x 16 rows = 128 rows; K chunked by 32. Writes RAW fp16 z.
__global__ void __launch_bounds__(256) k_gemm(const float* __restrict__ x, int N) {
    __shared__ unsigned xs[128][36];     // tf32 bits; pad 36 -> conflict-free A LDS
    __shared__ uint2    wf[4][8][32];    // B fragments [kstep][ntile][lane]

    int t = threadIdx.x;
    int w = t >> 5, lane = t & 31;
    int gid = lane >> 2, tig = lane & 3;
    int row0 = blockIdx.x * 128;

    float acc[8][4];
    #pragma unroll
    for (int i = 0; i < 8; i++)
        #pragma unroll
        for (int j = 0; j < 4; j++) acc[i][j] = 0.f;

    for (int kc = 0; kc < FIN; kc += 32) {
        __syncthreads();
        // B fragments: 4 ksteps x 8 ntiles x 32 lanes (g_Wc pre-rounded to tf32)
        #pragma unroll
        for (int i = 0; i < 4; i++) {
            int idx = t + i * 256;
            int ks = idx >> 8, nt = (idx >> 5) & 7, ln = idx & 31;
            int g = ln >> 2, tg = ln & 3;
            uint2 bb;
            bb.x = __float_as_uint(g_Wc[(kc + ks * 8 + tg) * FOUT + nt * 8 + g]);
            bb.y = __float_as_uint(g_Wc[(kc + ks * 8 + tg + 4) * FOUT + nt * 8 + g]);
            wf[ks][nt][ln] = bb;
        }
        // x tile: 128 rows x 32 k, coalesced float4 loads -> tf32 bits
        {
            int r = t >> 1, half = t & 1;
            int gr = row0 + r;
            const float4* p = (const float4*)&x[(size_t)gr * FIN + kc + half * 16];
            #pragma unroll
            for (int j = 0; j < 4; j++) {
                float4 v = (gr < N) ? p[j] : make_float4(0.f, 0.f, 0.f, 0.f);
                uint4 u;
                u.x = __float_as_uint(nvcuda::wmma::__float_to_tf32(v.x));
                u.y = __float_as_uint(nvcuda::wmma::__float_to_tf32(v.y));
                u.z = __float_as_uint(nvcuda::wmma::__float_to_tf32(v.z));
                u.w = __float_as_uint(nvcuda::wmma::__float_to_tf32(v.w));
                *(uint4*)&xs[r][half * 16 + j * 4] = u;
            }
        }
        __syncthreads();

        #pragma unroll
        for (int ks = 0; ks < 4; ks++) {
            int r = w * 16 + gid;
            unsigned a0 = xs[r][ks * 8 + tig];
            unsigned a1 = xs[r + 8][ks * 8 + tig];
            unsigned a2 = xs[r][ks * 8 + tig + 4];
            unsigned a3 = xs[r + 8][ks * 8 + tig + 4];
            #pragma unroll
            for (int nt = 0; nt < 8; nt++) {
                uint2 b = wf[ks][nt][lane];
                asm volatile(
                    "mma.sync.aligned.m16n8k8.row.col.f32.tf32.tf32.f32 "
                    "{%0,%1,%2,%3}, {%4,%5,%6,%7}, {%8,%9}, {%0,%1,%2,%3};"
                    : "+f"(acc[nt][0]), "+f"(acc[nt][1]),
                      "+f"(acc[nt][2]), "+f"(acc[nt][3])
                    : "r"(a0), "r"(a1), "r"(a2), "r"(a3), "r"(b.x), "r"(b.y));
            }
        }
    }

    // epilogue: raw fp16 z.  C-frag: {c0,c1}=(row gid, cols 2tig,2tig+1), {c2,c3}=(row gid+8)
    int rbase = row0 + w * 16 + gid;
    #pragma unroll
    for (int half = 0; half < 2; half++) {
        int r = rbase + half * 8;
        if (r < N) {
            #pragma unroll
            for (int nt = 0; nt < 8; nt++) {
                int col = nt * 8 + tig * 2;
                __half2 h = __float22half2_rn(
                    make_float2(acc[nt][half * 2 + 0], acc[nt][half * 2 + 1]));
                *(unsigned*)&g_zs[(size_t)r * FOUT + col] = *(unsigned*)&h;
            }
        }
    }
}

// ---------------------------------------------------------------------------
// zs[r] *= dis[r]  (in-place fp16, fp32 math). 8 threads per row.
__global__ void __launch_bounds__(256) k_scale(int N) {
    int gid = blockIdx.x * 256 + threadIdx.x;
    int row = gid >> 3;
    if (row >= N) return;
    float d = g_dis[row];
    uint4* p = (uint4*)&g_zs[(size_t)row * FOUT + (gid & 7) * 8];
    uint4 u = *p;
    unsigned* uu = (unsigned*)&u;
    #pragma unroll
    for (int i = 0; i < 4; i++) {
        float2 f = __half22float2(*reinterpret_cast<__half2*>(&uu[i]));
        __half2 h = __float22half2_rn(make_float2(d * f.x, d * f.y));
        uu[i] = *(unsigned*)&h;
    }
    *p = u;
}

// ---------------------------------------------------------------------------
// Aggregation incl. self-loop: out[c] = cb + dis[c] * (zs[c] + sum_r zs[r]).
__global__ void __launch_bounds__(256) k_aggr(float* __restrict__ out, int N) {
    int w = (blockIdx.x * 256 + threadIdx.x) >> 5;
    int lane = threadIdx.x & 31;
    if (w >= N) return;
    int c = w;
    int off0 = g_off[c], off1 = g_off[c + 1];

    unsigned us = *(const unsigned*)&g_zs[(size_t)c * FOUT + lane * 2];
    float2 acc = __half22float2(*reinterpret_cast<__half2*>(&us));

    for (int base = off0; base < off1; base += 32) {
        int cnt = min(32, off1 - base);
        int myE = base + lane;
        int rl = (lane < cnt) ? __ldg(&g_eidx[myE]) : 0;
        int j = 0;
        for (; j + 4 <= cnt; j += 4) {
            int r0 = __shfl_sync(0xffffffff, rl, j);
            int r1 = __shfl_sync(0xffffffff, rl, j + 1);
            int r2 = __shfl_sync(0xffffffff, rl, j + 2);
            int r3 = __shfl_sync(0xffffffff, rl, j + 3);
            unsigned u0 = *(const unsigned*)&g_zs[(size_t)r0 * FOUT + lane * 2];
            unsigned u1 = *(const unsigned*)&g_zs[(size_t)r1 * FOUT + lane * 2];
            unsigned u2 = *(const unsigned*)&g_zs[(size_t)r2 * FOUT + lane * 2];
            unsigned u3 = *(const unsigned*)&g_zs[(size_t)r3 * FOUT + lane * 2];
            float2 f0 = __half22float2(*reinterpret_cast<__half2*>(&u0));
            float2 f1 = __half22float2(*reinterpret_cast<__half2*>(&u1));
            float2 f2 = __half22float2(*reinterpret_cast<__half2*>(&u2));
            float2 f3 = __half22float2(*reinterpret_cast<__half2*>(&u3));
            acc.x += f0.x + f1.x + f2.x + f3.x;
            acc.y += f0.y + f1.y + f2.y + f3.y;
        }
        for (; j < cnt; j++) {
            int r = __shfl_sync(0xffffffff, rl, j);
            unsigned u = *(const unsigned*)&g_zs[(size_t)r * FOUT + lane * 2];
            float2 f = __half22float2(*reinterpret_cast<__half2*>(&u));
            acc.x += f.x; acc.y += f.y;
        }
    }
    float dc = g_dis[c];
    float2 cb = *(const float2*)&g_c[lane * 2];
    float2 ov;
    ov.x = cb.x + dc * acc.x;
    ov.y = cb.y + dc * acc.y;
    *(float2*)&out[(size_t)c * FOUT + lane * 2] = ov;
}

// ---------------------------------------------------------------------------
// Forked-stream schedule:
//   stream0: memset(deg) -> deg -> scan1 [eDis] -> scan3 -> fill -> [wait eSide] -> aggr
//   s2:      fuse_w -> gemm -> [wait eDis] -> scale [eSide]
extern "C" void kernel_launch(void* const* d_in, const int* in_sizes, int n_in,
                              void* d_out, int out_size) {
    const float* x  = (const float*)d_in[0];
    const int*   ei = (const int*)d_in[1];
    const float* Wg = (const float*)d_in[2];
    const float* bg = (const float*)d_in[3];
    const float* Wf = (const float*)d_in[4];
    const float* bf = (const float*)d_in[5];
    float* out = (float*)d_out;

    int N = in_sizes[0] / FIN;
    int E = in_sizes[1] / 2;
    const int* erow = ei;        // sources
    const int* ecol = ei + E;    // targets (aggregation index)

    int nb = (N + 255) / 256;

    cudaStream_t s2;
    cudaStreamCreateWithFlags(&s2, cudaStreamNonBlocking);
    cudaEvent_t eFork, eDis, eSide;
    cudaEventCreateWithFlags(&eFork, cudaEventDisableTiming);
    cudaEventCreateWithFlags(&eDis,  cudaEventDisableTiming);
    cudaEventCreateWithFlags(&eSide, cudaEventDisableTiming);

    void* degPtr = nullptr;
    cudaGetSymbolAddress(&degPtr, g_deg);

    // fork: dense pipeline on side stream
    cudaEventRecord(eFork, 0);
    cudaStreamWaitEvent(s2, eFork, 0);
    k_fuse_w<<<((FIN + 1) * FOUT * 32 + 255) / 256, 256, 0, s2>>>(Wg, bg, Wf, bf);
    k_gemm<<<(N + 127) / 128, 256, 0, s2>>>(x, N);

    // main branch: degree + CSR pipeline
    cudaMemsetAsync(degPtr, 0, (size_t)N * sizeof(int), 0);
    k_deg<<<(E + 255) / 256, 256>>>(ecol, E);
    k_scan1<<<nb, 256>>>(N);
    cudaEventRecord(eDis, 0);
    k_scan3<<<nb, 256>>>(N, E);
    k_fill<<<(E + 255) / 256, 256>>>(erow, ecol, E);

    // side branch: scale (needs gemm + dis)
    cudaStreamWaitEvent(s2, eDis, 0);
    k_scale<<<(N * 8 + 255) / 256, 256, 0, s2>>>(N);
    cudaEventRecord(eSide, s2);

    // join, aggregate
    cudaStreamWaitEvent(0, eSide, 0);
    k_aggr<<<(N * 32 + 255) / 256, 256>>>(out, N);
}

// round 12
// speedup vs baseline: 1.5518x; 1.0519x over previous
#include <cuda_runtime.h>
#include <cuda_fp16.h>
#include <mma.h>

#define NMAX 100000
#define FIN  128
#define FOUT 64
#define CAP  64                    // per-node bucket capacity (Poisson(16) tail ~1e-20)
#define OVFCAP (1 << 18)

// ---- scratch (static device globals; no allocations allowed) ----
__device__ int    g_deg[NMAX];
__device__ float  g_dis[NMAX];
__device__ __align__(128) __half g_zs[(size_t)NMAX * FOUT]; // fp16 z, then dis*z after k_scale
__device__ float  g_Wc[FIN * FOUT];            // fused weight (tf32-rounded)
__device__ float  g_c[FOUT];                   // fused bias (fp32)
__device__ int    g_list[(size_t)NMAX * CAP];  // bucketed source lists, 25.6 MB
__device__ int    g_ovfcnt;
__device__ int    g_ovf[2 * OVFCAP];           // (target, source) overflow pairs

// ---------------------------------------------------------------------------
// Single-pass bucket fill: counts degree AND records sources. Replaces
// the deg -> scan1 -> scan3 -> fill CSR chain.
__global__ void k_fill_direct(const int* __restrict__ erow,
                              const int* __restrict__ ecol, int E) {
    int i = blockIdx.x * blockDim.x + threadIdx.x;
    if (i >= E) return;
    int c = ecol[i];
    int r = erow[i];
    int slot = atomicAdd(&g_deg[c], 1);
    if (slot < CAP) {
        g_list[(size_t)c * CAP + slot] = r;
    } else {
        int o = atomicAdd(&g_ovfcnt, 1);
        if (o < OVFCAP) { g_ovf[2 * o] = c; g_ovf[2 * o + 1] = r; }
    }
}

// ---------------------------------------------------------------------------
// Wc[k][o] = sum_m W_gcn[k][m] * W_fc[o][m]  (stored tf32-rna-rounded)
// c[o]     = b_fc[o] + W_fc @ b_gcn           (full fp32)
__global__ void __launch_bounds__(256) k_fuse_w(const float* __restrict__ Wg,
                                                const float* __restrict__ bg,
                                                const float* __restrict__ Wf,
                                                const float* __restrict__ bf) {
    int w = (blockIdx.x * 256 + threadIdx.x) >> 5;
    int lane = threadIdx.x & 31;
    if (w >= (FIN + 1) * FOUT) return;
    int k = w >> 6;
    int o = w & 63;
    const float* wrow = (k < FIN) ? (Wg + (size_t)k * FIN) : bg;
    float s = 0.f;
    #pragma unroll
    for (int m = lane; m < FIN; m += 32) s += wrow[m] * Wf[(size_t)o * FIN + m];
    #pragma unroll
    for (int d = 16; d; d >>= 1) s += __shfl_xor_sync(0xffffffff, s, d);
    if (lane == 0) {
        if (k < FIN) g_Wc[k * FOUT + o] = nvcuda::wmma::__float_to_tf32(s);
        else         g_c[o] = s + bf[o];
    }
}

// ---------------------------------------------------------------------------
// z = x @ Wc via tf32 mma.sync m16n8k8 (round-11 proven). RAW fp16 z out.
__global__ void __launch_bounds__(256) k_gemm(const float* __restrict__ x, int N) {
    __shared__ unsigned xs[128][36];     // tf32 bits; pad 36 -> conflict-free A LDS
    __shared__ uint2    wf[4][8][32];    // B fragments [kstep][ntile][lane]

    int t = threadIdx.x;
    int w = t >> 5, lane = t & 31;
    int gid = lane >> 2, tig = lane & 3;
    int row0 = blockIdx.x * 128;

    float acc[8][4];
    #pragma unroll
    for (int i = 0; i < 8; i++)
        #pragma unroll
        for (int j = 0; j < 4; j++) acc[i][j] = 0.f;

    for (int kc = 0; kc < FIN; kc += 32) {
        __syncthreads();
        #pragma unroll
        for (int i = 0; i < 4; i++) {
            int idx = t + i * 256;
            int ks = idx >> 8, nt = (idx >> 5) & 7, ln = idx & 31;
            int g = ln >> 2, tg = ln & 3;
            uint2 bb;
            bb.x = __float_as_uint(g_Wc[(kc + ks * 8 + tg) * FOUT + nt * 8 + g]);
            bb.y = __float_as_uint(g_Wc[(kc + ks * 8 + tg + 4) * FOUT + nt * 8 + g]);
            wf[ks][nt][ln] = bb;
        }
        {
            int r = t >> 1, half = t & 1;
            int gr = row0 + r;
            const float4* p = (const float4*)&x[(size_t)gr * FIN + kc + half * 16];
            #pragma unroll
            for (int j = 0; j < 4; j++) {
                float4 v = (gr < N) ? p[j] : make_float4(0.f, 0.f, 0.f, 0.f);
                uint4 u;
                u.x = __float_as_uint(nvcuda::wmma::__float_to_tf32(v.x));
                u.y = __float_as_uint(nvcuda::wmma::__float_to_tf32(v.y));
                u.z = __float_as_uint(nvcuda::wmma::__float_to_tf32(v.z));
                u.w = __float_as_uint(nvcuda::wmma::__float_to_tf32(v.w));
                *(uint4*)&xs[r][half * 16 + j * 4] = u;
            }
        }
        __syncthreads();

        #pragma unroll
        for (int ks = 0; ks < 4; ks++) {
            int r = w * 16 + gid;
            unsigned a0 = xs[r][ks * 8 + tig];
            unsigned a1 = xs[r + 8][ks * 8 + tig];
            unsigned a2 = xs[r][ks * 8 + tig + 4];
            unsigned a3 = xs[r + 8][ks * 8 + tig + 4];
            #pragma unroll
            for (int nt = 0; nt < 8; nt++) {
                uint2 b = wf[ks][nt][lane];
                asm volatile(
                    "mma.sync.aligned.m16n8k8.row.col.f32.tf32.tf32.f32 "
                    "{%0,%1,%2,%3}, {%4,%5,%6,%7}, {%8,%9}, {%0,%1,%2,%3};"
                    : "+f"(acc[nt][0]), "+f"(acc[nt][1]),
                      "+f"(acc[nt][2]), "+f"(acc[nt][3])
                    : "r"(a0), "r"(a1), "r"(a2), "r"(a3), "r"(b.x), "r"(b.y));
            }
        }
    }

    int rbase = row0 + w * 16 + gid;
    #pragma unroll
    for (int half = 0; half < 2; half++) {
        int r = rbase + half * 8;
        if (r < N) {
            #pragma unroll
            for (int nt = 0; nt < 8; nt++) {
                int col = nt * 8 + tig * 2;
                __half2 h = __float22half2_rn(
                    make_float2(acc[nt][half * 2 + 0], acc[nt][half * 2 + 1]));
                *(unsigned*)&g_zs[(size_t)r * FOUT + col] = *(unsigned*)&h;
            }
        }
    }
}

// ---------------------------------------------------------------------------
// dis[r] = rsqrt(deg[r]+1); zs[r] *= dis[r]. 8 threads per row.
__global__ void __launch_bounds__(256) k_scale(int N) {
    int gid = blockIdx.x * 256 + threadIdx.x;
    int row = gid >> 3;
    if (row >= N) return;
    float d = rsqrtf((float)(g_deg[row] + 1));   // +1 self-loop
    if ((gid & 7) == 0) g_dis[row] = d;
    uint4* p = (uint4*)&g_zs[(size_t)row * FOUT + (gid & 7) * 8];
    uint4 u = *p;
    unsigned* uu = (unsigned*)&u;
    #pragma unroll
    for (int i = 0; i < 4; i++) {
        float2 f = __half22float2(*reinterpret_cast<__half2*>(&uu[i]));
        __half2 h = __float22half2_rn(make_float2(d * f.x, d * f.y));
        uu[i] = *(unsigned*)&h;
    }
    *p = u;
}

// ---------------------------------------------------------------------------
// Aggregation incl. self-loop: out[c] = cb + dis[c] * (zs[c] + sum_r zs[r]).
// One warp per node; sources from the bucket list (first CAP; rest via ovf).
__global__ void __launch_bounds__(256) k_aggr(float* __restrict__ out, int N) {
    int w = (blockIdx.x * 256 + threadIdx.x) >> 5;
    int lane = threadIdx.x & 31;
    if (w >= N) return;
    int c = w;
    int deg = min(g_deg[c], CAP);
    const int* lst = &g_list[(size_t)c * CAP];

    unsigned us = *(const unsigned*)&g_zs[(size_t)c * FOUT + lane * 2];
    float2 acc = __half22float2(*reinterpret_cast<__half2*>(&us));

    for (int base = 0; base < deg; base += 32) {
        int cnt = min(32, deg - base);
        int rl = (lane < cnt) ? __ldg(&lst[base + lane]) : 0;
        int j = 0;
        for (; j + 4 <= cnt; j += 4) {
            int r0 = __shfl_sync(0xffffffff, rl, j);
            int r1 = __shfl_sync(0xffffffff, rl, j + 1);
            int r2 = __shfl_sync(0xffffffff, rl, j + 2);
            int r3 = __shfl_sync(0xffffffff, rl, j + 3);
            unsigned u0 = *(const unsigned*)&g_zs[(size_t)r0 * FOUT + lane * 2];
            unsigned u1 = *(const unsigned*)&g_zs[(size_t)r1 * FOUT + lane * 2];
            unsigned u2 = *(const unsigned*)&g_zs[(size_t)r2 * FOUT + lane * 2];
            unsigned u3 = *(const unsigned*)&g_zs[(size_t)r3 * FOUT + lane * 2];
            float2 f0 = __half22float2(*reinterpret_cast<__half2*>(&u0));
            float2 f1 = __half22float2(*reinterpret_cast<__half2*>(&u1));
            float2 f2 = __half22float2(*reinterpret_cast<__half2*>(&u2));
            float2 f3 = __half22float2(*reinterpret_cast<__half2*>(&u3));
            acc.x += f0.x + f1.x + f2.x + f3.x;
            acc.y += f0.y + f1.y + f2.y + f3.y;
        }
        for (; j < cnt; j++) {
            int r = __shfl_sync(0xffffffff, rl, j);
            unsigned u = *(const unsigned*)&g_zs[(size_t)r * FOUT + lane * 2];
            float2 f = __half22float2(*reinterpret_cast<__half2*>(&u));
            acc.x += f.x; acc.y += f.y;
        }
    }
    float dc = g_dis[c];
    float2 cb = *(const float2*)&g_c[lane * 2];
    float2 ov;
    ov.x = cb.x + dc * acc.x;
    ov.y = cb.y + dc * acc.y;
    *(float2*)&out[(size_t)c * FOUT + lane * 2] = ov;
}

// ---------------------------------------------------------------------------
// Overflow edges (statistically zero): one warp per entry, RED-add into out.
__global__ void k_ovf(float* __restrict__ out) {
    int cnt = min(g_ovfcnt, OVFCAP);
    int lane = threadIdx.x & 31;
    int wstart = (blockIdx.x * blockDim.x + threadIdx.x) >> 5;
    int nw = (gridDim.x * blockDim.x) >> 5;
    for (int e = wstart; e < cnt; e += nw) {
        int c = g_ovf[2 * e];
        int r = g_ovf[2 * e + 1];
        float dc = g_dis[c];
        unsigned u = *(const unsigned*)&g_zs[(size_t)r * FOUT + lane * 2];
        float2 f = __half22float2(*reinterpret_cast<__half2*>(&u));
        atomicAdd(&out[(size_t)c * FOUT + lane * 2],     dc * f.x);
        atomicAdd(&out[(size_t)c * FOUT + lane * 2 + 1], dc * f.y);
    }
}

// ---------------------------------------------------------------------------
// Forked-stream schedule:
//   stream0: memset(deg,ovfcnt) -> fill_direct -> [wait eGemm] -> scale -> aggr -> ovf
//   s2:      fuse_w -> gemm [eGemm]
extern "C" void kernel_launch(void* const* d_in, const int* in_sizes, int n_in,
                              void* d_out, int out_size) {
    const float* x  = (const float*)d_in[0];
    const int*   ei = (const int*)d_in[1];
    const float* Wg = (const float*)d_in[2];
    const float* bg = (const float*)d_in[3];
    const float* Wf = (const float*)d_in[4];
    const float* bf = (const float*)d_in[5];
    float* out = (float*)d_out;

    int N = in_sizes[0] / FIN;
    int E = in_sizes[1] / 2;
    const int* erow = ei;        // sources
    const int* ecol = ei + E;    // targets (aggregation index)

    cudaStream_t s2;
    cudaStreamCreateWithFlags(&s2, cudaStreamNonBlocking);
    cudaEvent_t eFork, eGemm;
    cudaEventCreateWithFlags(&eFork, cudaEventDisableTiming);
    cudaEventCreateWithFlags(&eGemm, cudaEventDisableTiming);

    void* degPtr = nullptr; void* ovfPtr = nullptr;
    cudaGetSymbolAddress(&degPtr, g_deg);
    cudaGetSymbolAddress(&ovfPtr, g_ovfcnt);

    // fork: dense pipeline on side stream
    cudaEventRecord(eFork, 0);
    cudaStreamWaitEvent(s2, eFork, 0);
    k_fuse_w<<<((FIN + 1) * FOUT * 32 + 255) / 256, 256, 0, s2>>>(Wg, bg, Wf, bf);
    k_gemm<<<(N + 127) / 128, 256, 0, s2>>>(x, N);
    cudaEventRecord(eGemm, s2);

    // main branch: single-pass bucket fill
    cudaMemsetAsync(degPtr, 0, (size_t)N * sizeof(int), 0);
    cudaMemsetAsync(ovfPtr, 0, sizeof(int), 0);
    k_fill_direct<<<(E + 255) / 256, 256>>>(erow, ecol, E);

    // join: scale (needs gemm + final deg), aggregate, overflow fixup
    cudaStreamWaitEvent(0, eGemm, 0);
    k_scale<<<(N * 8 + 255) / 256, 256>>>(N);
    k_aggr<<<(N * 32 + 255) / 256, 256>>>(out, N);
    k_ovf<<<8, 256>>>(out);
}